// round 7
// baseline (speedup 1.0000x reference)
#include <cuda_runtime.h>

// Linear-chain CRF NLL, fused forward (log-partition) + gold score.
// B=4096, L=1024, T=32. One 32-thread block handles 2 batches packed as f32x2.
// 2-D matvec split: lane l = r + 8c owns prev-chunk {8c..8c+7} and row-slots
// s=0..3 mapped to rows r + 8*(c^s). Per step: 4 conflict-free LDS.128 load the
// chunk (padded layout, 80B chunk stride), 32 fma2 build 4 partials, then a
// SEL-free shfl_xor reduce-scatter (xor 16 then xor 8) leaves lane l holding
// finished row l. exp applied, exact power-of-2 renorm every 4 steps.
// 3-buffer register prefetch, distance 8 steps. One wave of 2048 warps.

namespace {

constexpr int T_ = 32;
constexpr int L_ = 1024;
constexpr int START_ = 30;
constexpr int STOP_ = 31;
constexpr unsigned FULL_ = 0xffffffffu;
typedef unsigned long long u64;

__device__ __forceinline__ u64 pack2(float lo, float hi) {
    u64 r;
    asm("mov.b64 %0, {%1, %2};" : "=l"(r) : "f"(lo), "f"(hi));
    return r;
}
__device__ __forceinline__ void unpack2(u64 v, float& lo, float& hi) {
    asm("mov.b64 {%0, %1}, %2;" : "=f"(lo), "=f"(hi) : "l"(v));
}
__device__ __forceinline__ void fma2(u64& acc, u64 a, u64 b) {
    asm("fma.rn.f32x2 %0, %1, %2, %0;" : "+l"(acc) : "l"(a), "l"(b));
}
__device__ __forceinline__ u64 add2(u64 a, u64 b) {
    u64 r;
    asm("add.rn.f32x2 %0, %1, %2;" : "=l"(r) : "l"(a), "l"(b));
    return r;
}
__device__ __forceinline__ u64 mul2(u64 a, u64 b) {
    u64 r;
    asm("mul.rn.f32x2 %0, %1, %2;" : "=l"(r) : "l"(a), "l"(b));
    return r;
}

// Exact power-of-two renormalization; positive floats compare as unsigned ints.
__device__ __forceinline__ void renorm_pair(u64& v, int& se0, int& se1) {
    unsigned lo = (unsigned)v;
    unsigned hi = (unsigned)(v >> 32);
    unsigned m0 = __reduce_max_sync(FULL_, lo);
    unsigned m1 = __reduce_max_sync(FULL_, hi);
    int e0 = (int)(m0 >> 23) - 127;
    int e1 = (int)(m1 >> 23) - 127;
    e0 = max(-64, min(e0, 120));
    e1 = max(-64, min(e1, 120));
    unsigned s0 = (unsigned)(127 - e0) << 23;  // 2^-e0
    unsigned s1 = (unsigned)(127 - e1) << 23;  // 2^-e1
    v = mul2(v, (u64)s0 | ((u64)s1 << 32));
    se0 += e0;
    se1 += e1;
}

// Padded SMEM index for state p: chunk (p>>3) strided by 10 u64 (80 B) so the
// four 16B-chunk reads per LDS.128 hit disjoint bank groups.
__device__ __forceinline__ int svidx(int p) { return (p >> 3) * 10 + (p & 7); }

template <int TS>
__device__ __forceinline__ void crf_body(const float* __restrict__ feats,
                                         const float* __restrict__ trans,
                                         const unsigned* __restrict__ tagw,
                                         float* __restrict__ out,
                                         u64 (*sv)[40]) {
    const int t = threadIdx.x;
    const int r = t & 7;
    const int c = t >> 3;
    const int b0 = blockIdx.x * 2;
    const int myidx = svidx(t);

    // E2[s][k] = exp(trans[row(s)][8c+k]) packed {e,e}, row(s) = r + 8*(c^s).
    u64 E2[4][8];
#pragma unroll
    for (int s = 0; s < 4; ++s) {
        const int row = r + 8 * (c ^ s);
#pragma unroll
        for (int k = 0; k < 8; ++k) {
            float e = __expf(__ldg(trans + row * T_ + 8 * c + k));
            E2[s][k] = pack2(e, e);
        }
    }

    // Initial fv (linear domain): v[START]=1, else 0. Lane t owns state t.
    {
        float vi = (t == START_) ? 1.0f : 0.0f;
        sv[0][myidx] = pack2(vi, vi);
    }

    const float* fb0 = feats + (size_t)b0 * L_ * T_ + t;
    const float* fb1 = fb0 + (size_t)L_ * T_;
    const unsigned* tb0 = tagw + (size_t)b0 * L_ * TS;
    const unsigned* tb1 = tb0 + (size_t)L_ * TS;

    float F0[3][4], F1[3][4];  // feat prefetch [buf][step]
    unsigned P0[3], P1[3];     // 4 tags byte-packed per buf per batch

    int sc0 = 0, sc1 = 0;
    float gt0 = 0.f, gt1 = 0.f, ge0 = 0.f, ge1 = 0.f;
    unsigned pv0 = START_, pv1 = START_;
    u64 vcur = 0ULL;  // this lane's current fv value (row t)

#define PF(I, G)                                                               \
    do {                                                                       \
        const int gc_ = ((G) < 256) ? (G) : 255;                               \
        const float* q0_ = fb0 + gc_ * 128;                                    \
        const float* q1_ = fb1 + gc_ * 128;                                    \
        _Pragma("unroll") for (int s_ = 0; s_ < 4; ++s_) {                     \
            F0[I][s_] = __ldg(q0_ + s_ * 32);                                  \
            F1[I][s_] = __ldg(q1_ + s_ * 32);                                  \
        }                                                                      \
        if (TS == 1) {                                                         \
            uint4 w0_ = __ldg((const uint4*)(tb0 + gc_ * 4));                  \
            uint4 w1_ = __ldg((const uint4*)(tb1 + gc_ * 4));                  \
            P0[I] = w0_.x | (w0_.y << 8) | (w0_.z << 16) | (w0_.w << 24);      \
            P1[I] = w1_.x | (w1_.y << 8) | (w1_.z << 16) | (w1_.w << 24);      \
        } else {                                                               \
            uint4 a0_ = __ldg((const uint4*)(tb0 + gc_ * 8));                  \
            uint4 a1_ = __ldg((const uint4*)(tb0 + gc_ * 8 + 4));              \
            uint4 c0_ = __ldg((const uint4*)(tb1 + gc_ * 8));                  \
            uint4 c1_ = __ldg((const uint4*)(tb1 + gc_ * 8 + 4));              \
            P0[I] = a0_.x | (a0_.z << 8) | (a1_.x << 16) | (a1_.z << 24);      \
            P1[I] = c0_.x | (c0_.z << 8) | (c1_.x << 16) | (c1_.z << 24);      \
        }                                                                      \
    } while (0)

#define STEP(I, S, CUR, NXT, RN)                                               \
    do {                                                                       \
        const float f0_ = F0[I][S], f1_ = F1[I][S];                            \
        const u64 ef_ = pack2(__expf(f0_), __expf(f1_));                       \
        const u64* base_ = &sv[CUR][c * 10];                                   \
        const ulonglong2 w01_ = *(const ulonglong2*)(base_ + 0);               \
        const ulonglong2 w23_ = *(const ulonglong2*)(base_ + 2);               \
        const ulonglong2 w45_ = *(const ulonglong2*)(base_ + 4);               \
        const ulonglong2 w67_ = *(const ulonglong2*)(base_ + 6);               \
        u64 a0_ = 0ULL, a1_ = 0ULL, a2_ = 0ULL, a3_ = 0ULL;                    \
        fma2(a0_, w01_.x, E2[0][0]); fma2(a1_, w01_.x, E2[1][0]);              \
        fma2(a2_, w01_.x, E2[2][0]); fma2(a3_, w01_.x, E2[3][0]);              \
        fma2(a0_, w01_.y, E2[0][1]); fma2(a1_, w01_.y, E2[1][1]);              \
        fma2(a2_, w01_.y, E2[2][1]); fma2(a3_, w01_.y, E2[3][1]);              \
        fma2(a0_, w23_.x, E2[0][2]); fma2(a1_, w23_.x, E2[1][2]);              \
        fma2(a2_, w23_.x, E2[2][2]); fma2(a3_, w23_.x, E2[3][2]);              \
        fma2(a0_, w23_.y, E2[0][3]); fma2(a1_, w23_.y, E2[1][3]);              \
        fma2(a2_, w23_.y, E2[2][3]); fma2(a3_, w23_.y, E2[3][3]);              \
        fma2(a0_, w45_.x, E2[0][4]); fma2(a1_, w45_.x, E2[1][4]);              \
        fma2(a2_, w45_.x, E2[2][4]); fma2(a3_, w45_.x, E2[3][4]);              \
        fma2(a0_, w45_.y, E2[0][5]); fma2(a1_, w45_.y, E2[1][5]);              \
        fma2(a2_, w45_.y, E2[2][5]); fma2(a3_, w45_.y, E2[3][5]);              \
        fma2(a0_, w67_.x, E2[0][6]); fma2(a1_, w67_.x, E2[1][6]);              \
        fma2(a2_, w67_.x, E2[2][6]); fma2(a3_, w67_.x, E2[3][6]);              \
        fma2(a0_, w67_.y, E2[0][7]); fma2(a1_, w67_.y, E2[1][7]);              \
        fma2(a2_, w67_.y, E2[2][7]); fma2(a3_, w67_.y, E2[3][7]);              \
        /* reduce-scatter: xor16 merges chunk c^2, xor8 merges c^1 (+c^3) */   \
        a0_ = add2(a0_, __shfl_xor_sync(FULL_, a2_, 16));                      \
        a1_ = add2(a1_, __shfl_xor_sync(FULL_, a3_, 16));                      \
        a0_ = add2(a0_, __shfl_xor_sync(FULL_, a1_, 8));                       \
        u64 v_ = mul2(a0_, ef_);                                               \
        if (RN) renorm_pair(v_, sc0, sc1);                                     \
        vcur = v_;                                                             \
        sv[NXT][myidx] = v_;                                                   \
        const unsigned g0_ = (P0[I] >> (8 * (S))) & 0xffu;                     \
        const unsigned g1_ = (P1[I] >> (8 * (S))) & 0xffu;                     \
        gt0 += __ldg(trans + g0_ * 32u + pv0);                                 \
        pv0 = g0_;                                                             \
        gt1 += __ldg(trans + g1_ * 32u + pv1);                                 \
        pv1 = g1_;                                                             \
        ge0 += (t == (int)g0_) ? f0_ : 0.0f;                                   \
        ge1 += (t == (int)g1_) ? f1_ : 0.0f;                                   \
        __syncthreads();                                                       \
    } while (0)

#define GROUP(I)                                                               \
    do {                                                                       \
        STEP(I, 0, 0, 1, false);                                               \
        STEP(I, 1, 1, 0, false);                                               \
        STEP(I, 2, 0, 1, false);                                               \
        STEP(I, 3, 1, 0, true);                                                \
    } while (0)

    // Prologue: fill the three prefetch buffers, make init stores visible.
    PF(0, 0);
    PF(1, 1);
    PF(2, 2);
    __syncthreads();

    GROUP(0);  // group 0 (steps 0..3); step 0 works directly off the init fv

    // Groups 1..255, 3-phase rotation, prefetch 2 groups ahead.
#pragma unroll 1
    for (int it = 0; it < 85; ++it) {
        const int gg = 1 + it * 3;
        PF(0, gg + 2);
        GROUP(1);
        PF(1, gg + 3);
        GROUP(2);
        PF(2, gg + 4);
        GROUP(0);
    }

#undef PF
#undef STEP
#undef GROUP

    // Epilogue: alpha = log( sum_t v[t]*exp(trans[STOP,t]) ) + sc*ln2.
    u64 v = vcur;
    {
        const float es = __expf(__ldg(trans + STOP_ * T_ + t));
        v = mul2(v, pack2(es, es));
    }
#pragma unroll
    for (int o = 16; o > 0; o >>= 1) v = add2(v, __shfl_xor_sync(FULL_, v, o));
    u64 gep = pack2(ge0, ge1);
#pragma unroll
    for (int o = 16; o > 0; o >>= 1) gep = add2(gep, __shfl_xor_sync(FULL_, gep, o));

    if (t == 0) {
        float z0, z1, e0, e1;
        unpack2(v, z0, z1);
        unpack2(gep, e0, e1);
        const float LN2 = 0.6931471805599453f;
        const float a0 = __logf(z0) + (float)sc0 * LN2;
        const float a1 = __logf(z1) + (float)sc1 * LN2;
        const float go0 = gt0 + e0 + __ldg(trans + STOP_ * 32u + pv0);
        const float go1 = gt1 + e1 + __ldg(trans + STOP_ * 32u + pv1);
        *(float2*)(out + b0) = make_float2(a0 - go0, a1 - go1);
    }
}

__global__ void __launch_bounds__(32, 14) crf_fwd(const float* __restrict__ feats,
                                                  const float* __restrict__ trans,
                                                  const unsigned* __restrict__ tagw,
                                                  float* __restrict__ out) {
    __shared__ __align__(16) u64 sv[2][40];  // padded: state p at (p>>3)*10+(p&7)
    // Tag dtype detection: int64 tags (values < 30) have all-zero odd words.
    unsigned oddw = __ldg(tagw + 2 * threadIdx.x + 1);
    if (__any_sync(FULL_, oddw != 0)) {
        crf_body<1>(feats, trans, tagw, out, sv);  // int32 tags
    } else {
        crf_body<2>(feats, trans, tagw, out, sv);  // int64 tags
    }
}

}  // namespace

extern "C" void kernel_launch(void* const* d_in, const int* in_sizes, int n_in,
                              void* d_out, int out_size) {
    const float* feats = (const float*)d_in[0];
    const float* trans = (const float*)d_in[1];
    const unsigned* tagw = (const unsigned*)d_in[2];
    float* out = (float*)d_out;

    const int B = in_sizes[2] / L_;  // element count = B*L for either tag dtype
    crf_fwd<<<B / 2, 32>>>(feats, trans, tagw, out);
}

// round 9
// speedup vs baseline: 1.1245x; 1.1245x over previous
#include <cuda_runtime.h>

// Linear-chain CRF NLL, fused forward (log-partition) + bulk gold score.
// B=4096, L=1024, T=32. One 32-thread block handles 2 batches packed as f32x2.
// Forward loop: lane l = r + 8c owns prev-chunk {8c..8c+7} and row-slots
// s=0..3 -> rows r + 8*(c^s); 4 conflict-free LDS.128, 32 fma2, shfl_xor
// reduce-scatter (xor16, xor8), exact power-of-2 renorm every 4 steps.
// Gold score computed AFTER the loop as a vectorized gather phase (lanes
// sweep 32 l's per iter, shfl_up for prev tag) -> recurrence loop carries
// zero gold overhead. 3-buffer feat prefetch, distance 8 steps.

namespace {

constexpr int T_ = 32;
constexpr int L_ = 1024;
constexpr int START_ = 30;
constexpr int STOP_ = 31;
constexpr unsigned FULL_ = 0xffffffffu;
typedef unsigned long long u64;

__device__ __forceinline__ u64 pack2(float lo, float hi) {
    u64 r;
    asm("mov.b64 %0, {%1, %2};" : "=l"(r) : "f"(lo), "f"(hi));
    return r;
}
__device__ __forceinline__ void unpack2(u64 v, float& lo, float& hi) {
    asm("mov.b64 {%0, %1}, %2;" : "=f"(lo), "=f"(hi) : "l"(v));
}
__device__ __forceinline__ void fma2(u64& acc, u64 a, u64 b) {
    asm("fma.rn.f32x2 %0, %1, %2, %0;" : "+l"(acc) : "l"(a), "l"(b));
}
__device__ __forceinline__ u64 add2(u64 a, u64 b) {
    u64 r;
    asm("add.rn.f32x2 %0, %1, %2;" : "=l"(r) : "l"(a), "l"(b));
    return r;
}
__device__ __forceinline__ u64 mul2(u64 a, u64 b) {
    u64 r;
    asm("mul.rn.f32x2 %0, %1, %2;" : "=l"(r) : "l"(a), "l"(b));
    return r;
}

// Exact power-of-two renormalization; positive floats compare as unsigned ints.
__device__ __forceinline__ void renorm_pair(u64& v, int& se0, int& se1) {
    unsigned lo = (unsigned)v;
    unsigned hi = (unsigned)(v >> 32);
    unsigned m0 = __reduce_max_sync(FULL_, lo);
    unsigned m1 = __reduce_max_sync(FULL_, hi);
    int e0 = (int)(m0 >> 23) - 127;
    int e1 = (int)(m1 >> 23) - 127;
    e0 = max(-64, min(e0, 120));
    e1 = max(-64, min(e1, 120));
    unsigned s0 = (unsigned)(127 - e0) << 23;  // 2^-e0
    unsigned s1 = (unsigned)(127 - e1) << 23;  // 2^-e1
    v = mul2(v, (u64)s0 | ((u64)s1 << 32));
    se0 += e0;
    se1 += e1;
}

// Padded SMEM index for state p: chunk (p>>3) strided by 10 u64 (80 B).
__device__ __forceinline__ int svidx(int p) { return (p >> 3) * 10 + (p & 7); }

template <int TS>
__device__ __forceinline__ void crf_body(const float* __restrict__ feats,
                                         const float* __restrict__ trans,
                                         const unsigned* __restrict__ tagw,
                                         float* __restrict__ out,
                                         u64 (*sv)[40]) {
    const int t = threadIdx.x;
    const int r = t & 7;
    const int c = t >> 3;
    const int b0 = blockIdx.x * 2;
    const int myidx = svidx(t);

    // E2[s][k] = exp(trans[row(s)][8c+k]) packed {e,e}, row(s) = r + 8*(c^s).
    u64 E2[4][8];
#pragma unroll
    for (int s = 0; s < 4; ++s) {
        const int row = r + 8 * (c ^ s);
#pragma unroll
        for (int k = 0; k < 8; ++k) {
            float e = __expf(__ldg(trans + row * T_ + 8 * c + k));
            E2[s][k] = pack2(e, e);
        }
    }

    // Initial fv (linear domain): v[START]=1, else 0. Lane t owns state t.
    {
        float vi = (t == START_) ? 1.0f : 0.0f;
        sv[0][myidx] = pack2(vi, vi);
    }

    const float* fb0 = feats + (size_t)b0 * L_ * T_ + t;
    const float* fb1 = fb0 + (size_t)L_ * T_;

    float F0[3][4], F1[3][4];  // feat prefetch [buf][step]
    int sc0 = 0, sc1 = 0;
    u64 vcur = 0ULL;  // this lane's current fv value (row t)

#define PF(I, G)                                                               \
    do {                                                                       \
        const int gc_ = ((G) < 256) ? (G) : 255;                               \
        const float* q0_ = fb0 + gc_ * 128;                                    \
        const float* q1_ = fb1 + gc_ * 128;                                    \
        _Pragma("unroll") for (int s_ = 0; s_ < 4; ++s_) {                     \
            F0[I][s_] = __ldg(q0_ + s_ * 32);                                  \
            F1[I][s_] = __ldg(q1_ + s_ * 32);                                  \
        }                                                                      \
    } while (0)

#define STEP(I, S, CUR, NXT, RN)                                               \
    do {                                                                       \
        const u64 ef_ = pack2(__expf(F0[I][S]), __expf(F1[I][S]));             \
        const u64* base_ = &sv[CUR][c * 10];                                   \
        const ulonglong2 w01_ = *(const ulonglong2*)(base_ + 0);               \
        const ulonglong2 w23_ = *(const ulonglong2*)(base_ + 2);               \
        const ulonglong2 w45_ = *(const ulonglong2*)(base_ + 4);               \
        const ulonglong2 w67_ = *(const ulonglong2*)(base_ + 6);               \
        u64 a0_ = 0ULL, a1_ = 0ULL, a2_ = 0ULL, a3_ = 0ULL;                    \
        fma2(a0_, w01_.x, E2[0][0]); fma2(a1_, w01_.x, E2[1][0]);              \
        fma2(a2_, w01_.x, E2[2][0]); fma2(a3_, w01_.x, E2[3][0]);              \
        fma2(a0_, w01_.y, E2[0][1]); fma2(a1_, w01_.y, E2[1][1]);              \
        fma2(a2_, w01_.y, E2[2][1]); fma2(a3_, w01_.y, E2[3][1]);              \
        fma2(a0_, w23_.x, E2[0][2]); fma2(a1_, w23_.x, E2[1][2]);              \
        fma2(a2_, w23_.x, E2[2][2]); fma2(a3_, w23_.x, E2[3][2]);              \
        fma2(a0_, w23_.y, E2[0][3]); fma2(a1_, w23_.y, E2[1][3]);              \
        fma2(a2_, w23_.y, E2[2][3]); fma2(a3_, w23_.y, E2[3][3]);              \
        fma2(a0_, w45_.x, E2[0][4]); fma2(a1_, w45_.x, E2[1][4]);              \
        fma2(a2_, w45_.x, E2[2][4]); fma2(a3_, w45_.x, E2[3][4]);              \
        fma2(a0_, w45_.y, E2[0][5]); fma2(a1_, w45_.y, E2[1][5]);              \
        fma2(a2_, w45_.y, E2[2][5]); fma2(a3_, w45_.y, E2[3][5]);              \
        fma2(a0_, w67_.x, E2[0][6]); fma2(a1_, w67_.x, E2[1][6]);              \
        fma2(a2_, w67_.x, E2[2][6]); fma2(a3_, w67_.x, E2[3][6]);              \
        fma2(a0_, w67_.y, E2[0][7]); fma2(a1_, w67_.y, E2[1][7]);              \
        fma2(a2_, w67_.y, E2[2][7]); fma2(a3_, w67_.y, E2[3][7]);              \
        /* reduce-scatter: xor16 merges chunk c^2, xor8 merges c^1 (+c^3) */   \
        a0_ = add2(a0_, __shfl_xor_sync(FULL_, a2_, 16));                      \
        a1_ = add2(a1_, __shfl_xor_sync(FULL_, a3_, 16));                      \
        a0_ = add2(a0_, __shfl_xor_sync(FULL_, a1_, 8));                       \
        u64 v_ = mul2(a0_, ef_);                                               \
        if (RN) renorm_pair(v_, sc0, sc1);                                     \
        vcur = v_;                                                             \
        sv[NXT][myidx] = v_;                                                   \
        __syncthreads();                                                       \
    } while (0)

#define GROUP(I)                                                               \
    do {                                                                       \
        STEP(I, 0, 0, 1, false);                                               \
        STEP(I, 1, 1, 0, false);                                               \
        STEP(I, 2, 0, 1, false);                                               \
        STEP(I, 3, 1, 0, true);                                                \
    } while (0)

    // Prologue: fill the three prefetch buffers, make init stores visible.
    PF(0, 0);
    PF(1, 1);
    PF(2, 2);
    __syncthreads();

    GROUP(0);  // steps 0..3, works directly off the init fv

    // Groups 1..255, 3-phase rotation, prefetch 2 groups ahead.
#pragma unroll 1
    for (int it = 0; it < 85; ++it) {
        const int gg = 1 + it * 3;
        PF(0, gg + 2);
        GROUP(1);
        PF(1, gg + 3);
        GROUP(2);
        PF(2, gg + 4);
        GROUP(0);
    }

#undef PF
#undef STEP
#undef GROUP

    // ---- bulk gold score: gold = sum_l trans[g_l, g_{l-1}] + feat[l, g_l],
    // plus trans[STOP, g_{L-1}]. Lanes sweep 32 consecutive l per iteration.
    float gold0, gold1;
#pragma unroll
    for (int s = 0; s < 2; ++s) {
        const unsigned* tb = tagw + (size_t)(b0 + s) * L_ * TS;
        const float* fb = feats + (size_t)(b0 + s) * L_ * T_;
        unsigned carry = START_;
        float acc = 0.f;
#pragma unroll 4
        for (int it = 0; it < 32; ++it) {
            const int l = it * 32 + t;
            unsigned g = (TS == 1) ? __ldg(tb + l) : __ldg(tb + 2 * l);
            unsigned prev = __shfl_up_sync(FULL_, g, 1);
            if (t == 0) prev = carry;
            carry = __shfl_sync(FULL_, g, 31);
            acc += __ldg(trans + g * 32u + prev) + __ldg(fb + (size_t)l * 32 + g);
        }
        if (t == 0) acc += __ldg(trans + STOP_ * 32u + carry);
#pragma unroll
        for (int o = 16; o > 0; o >>= 1) acc += __shfl_xor_sync(FULL_, acc, o);
        if (s == 0) gold0 = acc; else gold1 = acc;
    }

    // ---- epilogue: alpha = log( sum_t v[t]*exp(trans[STOP,t]) ) + sc*ln2 ----
    u64 v = vcur;
    {
        const float es = __expf(__ldg(trans + STOP_ * T_ + t));
        v = mul2(v, pack2(es, es));
    }
#pragma unroll
    for (int o = 16; o > 0; o >>= 1) v = add2(v, __shfl_xor_sync(FULL_, v, o));

    if (t == 0) {
        float z0, z1;
        unpack2(v, z0, z1);
        const float LN2 = 0.6931471805599453f;
        const float a0 = __logf(z0) + (float)sc0 * LN2;
        const float a1 = __logf(z1) + (float)sc1 * LN2;
        *(float2*)(out + b0) = make_float2(a0 - gold0, a1 - gold1);
    }
}

__global__ void __launch_bounds__(32, 14) crf_fwd(const float* __restrict__ feats,
                                                  const float* __restrict__ trans,
                                                  const unsigned* __restrict__ tagw,
                                                  float* __restrict__ out) {
    __shared__ __align__(16) u64 sv[2][40];  // padded: state p at (p>>3)*10+(p&7)
    // Tag dtype detection: int64 tags (values < 30) have all-zero odd words.
    unsigned oddw = __ldg(tagw + 2 * threadIdx.x + 1);
    if (__any_sync(FULL_, oddw != 0)) {
        crf_body<1>(feats, trans, tagw, out, sv);  // int32 tags
    } else {
        crf_body<2>(feats, trans, tagw, out, sv);  // int64 tags
    }
}

}  // namespace

extern "C" void kernel_launch(void* const* d_in, const int* in_sizes, int n_in,
                              void* d_out, int out_size) {
    const float* feats = (const float*)d_in[0];
    const float* trans = (const float*)d_in[1];
    const unsigned* tagw = (const unsigned*)d_in[2];
    float* out = (float*)d_out;

    const int B = in_sizes[2] / L_;  // element count = B*L for either tag dtype
    crf_fwd<<<B / 2, 32>>>(feats, trans, tagw, out);
}